// round 12
// baseline (speedup 1.0000x reference)
#include <cuda_runtime.h>
#include <cuda_bf16.h>
#include <string.h>
#include <math.h>

// ---------------- problem constants ----------------
#define EID   30000
#define EMB   256
#define HID   512
#define SRC_T 128
#define TRG_T 50
#define B     64
#define G3    (3*HID)          // 1536
#define NLOG  30512            // 30000 logits cols + 512 Yh cols
#define LTIL  318              // ceil(30512/96)

// ---------------- device state ----------------
__device__ float g_hT[2 * HID * B];                    // hidden, transposed [j][b], double buffered
__device__ float g_giEnc[(size_t)SRC_T * G3 * B];      // encoder gi, [t][j][b] (incl. b_ih)
__device__ float g_logits[(size_t)B * EID];
__device__ float g_embT[(size_t)EMB * EID];            // emb_mt transposed
__device__ float g_mtProj[(size_t)EID * HID];          // W_r1[:, :256] @ emb_mt[v]
__device__ float g_Yh[B * HID];                        // W_r1[:, 256:768] @ h
__device__ float g_pm[B * 5], g_ps[B * 5];
__device__ int   g_pi[B * 5];
__device__ float g_rate[B];
__device__ int   g_idx[B];

// ---------------- packed fp32 FMA (sm_100+) ----------------
__device__ __forceinline__ float2 ffma2(float2 a, float2 b, float2 c) {
    unsigned long long ua, ub, uc, ud;
    memcpy(&ua, &a, 8); memcpy(&ub, &b, 8); memcpy(&uc, &c, 8);
    asm("fma.rn.f32x2 %0, %1, %2, %3;" : "=l"(ud) : "l"(ua), "l"(ub), "l"(uc));
    float2 d; memcpy(&d, &ud, 8); return d;
}

__device__ __forceinline__ float sigf(float x) { return 1.f / (1.f + expf(-x)); }

// ---------------- prep kernels ----------------
__global__ void init_state(const int* __restrict__ trg_eid, const float* __restrict__ trg_rate)
{
    int i = blockIdx.x * 256 + threadIdx.x;
    if (i < HID * B) g_hT[i] = 0.f;
    if (i < B) { g_idx[i] = trg_eid[i]; g_rate[i] = trg_rate[i]; }
}

// gi[t][j][b] = b_ih[j] + sum_k src[t][b][k] * W_ih[j][k]
__global__ void enc_gi(const float* __restrict__ src, const float* __restrict__ W_ih,
                       const float* __restrict__ b_ih)
{
    const int j = blockIdx.x * 4 + (threadIdx.x >> 6);
    const int b = threadIdx.x & 63;
    const int t = blockIdx.y;
    const float* x = src + ((size_t)t * 64 + b) * 3;
    float v = b_ih[j] + x[0] * W_ih[j * 3] + x[1] * W_ih[j * 3 + 1] + x[2] * W_ih[j * 3 + 2];
    g_giEnc[((size_t)t * G3 + j) * 64 + b] = v;
}

__global__ void transpose_emb(const float* __restrict__ emb_mt) {
    __shared__ float sm[32][33];
    int v0 = blockIdx.x * 32, k0 = blockIdx.y * 32;
    int tx = threadIdx.x & 31, ty = threadIdx.x >> 5;   // 256 threads: ty 0..7
    #pragma unroll
    for (int i = 0; i < 32; i += 8) {
        int v = v0 + ty + i;
        sm[ty + i][tx] = (v < EID) ? emb_mt[(size_t)v * EMB + k0 + tx] : 0.f;
    }
    __syncthreads();
    #pragma unroll
    for (int i = 0; i < 32; i += 8) {
        int v = v0 + tx;
        if (v < EID) g_embT[(size_t)(k0 + ty + i) * EID + v] = sm[tx][ty + i];
    }
}

// g_mtProj[v][j] = sum_{k<256} emb_mt[v][k] * W_r1[j][k]   (proven R8 kernel)
__global__ void mtproj_kernel(const float* __restrict__ W_r1) {
    __shared__ float xs[64 * 66];
    __shared__ float ws[64 * 65];
    int tid = threadIdx.x;
    int vt = blockIdx.x % 469, jt = blockIdx.x / 469;
    int v0 = vt * 64, j0 = jt * 64;
    int bpg = tid & 7, cg = tid >> 3;
    float2 acc[4][4];
    #pragma unroll
    for (int i = 0; i < 4; i++)
        #pragma unroll
        for (int c = 0; c < 4; c++) acc[i][c] = make_float2(0.f, 0.f);
    for (int kt = 0; kt < 256; kt += 64) {
        __syncthreads();
        for (int e = tid; e < 4096; e += 128) {
            int k = e >> 6, vl = e & 63; int v = v0 + vl;
            xs[k * 66 + vl] = (v < EID) ? g_embT[(size_t)(kt + k) * EID + v] : 0.f;
        }
        for (int e = tid; e < 4096; e += 128) {
            int nl = e >> 6, k = e & 63;
            ws[nl * 65 + k] = W_r1[(size_t)(j0 + nl) * 768 + kt + k];
        }
        __syncthreads();
        #pragma unroll 4
        for (int k = 0; k < 64; k++) {
            float2 xv[4];
            #pragma unroll
            for (int i = 0; i < 4; i++)
                xv[i] = *reinterpret_cast<const float2*>(&xs[k * 66 + 2 * (bpg + 8 * i)]);
            #pragma unroll
            for (int c = 0; c < 4; c++) {
                float w = ws[(cg * 4 + c) * 65 + k];
                float2 wp = make_float2(w, w);
                #pragma unroll
                for (int i = 0; i < 4; i++) acc[i][c] = ffma2(xv[i], wp, acc[i][c]);
            }
        }
    }
    #pragma unroll
    for (int c = 0; c < 4; c++) {
        int j = j0 + cg * 4 + c;
        #pragma unroll
        for (int i = 0; i < 4; i++) {
            int v = v0 + 2 * (bpg + 8 * i);
            if (v < EID)     g_mtProj[(size_t)v * HID + j]       = acc[i][c].x;
            if (v + 1 < EID) g_mtProj[(size_t)(v + 1) * HID + j] = acc[i][c].y;
        }
    }
}

// ---------------- fused encoder GRU step: 1 node ----------------
// 128 blocks x 128 thr. Block owns 4 j (all 3 gates), full K=512. smem 21KB.
__global__ __launch_bounds__(128)
void enc_fused(const float* __restrict__ hin, float* __restrict__ hout,
               const float* __restrict__ W_hh, const float* __restrict__ b_hh,
               const int* __restrict__ src_len, int t)
{
    __shared__ __align__(16) float xs[64 * 66];
    __shared__ __align__(16) float ws4[4 * 64 * 4];    // [jj][k][4] gates r,z,n
    const int tid = threadIdx.x;
    const int j0 = blockIdx.x * 4;
    const int jl = tid >> 5, lane = tid & 31;

    float2 aR = make_float2(0.f, 0.f), aZ = aR, aN = aR;
    for (int kt = 0; kt < HID; kt += 64) {
        __syncthreads();
        for (int e = tid; e < 4096; e += 128) {
            int k = e >> 6, b = e & 63;
            xs[k * 66 + b] = hin[(kt + k) * 64 + b];
        }
        for (int e = tid; e < 768; e += 128) {     // 4 jj x 3 g x 64 k
            int jj = e / 192, g = (e >> 6) % 3, k = e & 63;
            ws4[((jj << 6) + k) * 4 + g] = W_hh[(size_t)((g << 9) + j0 + jj) * HID + kt + k];
        }
        __syncthreads();
        const float* wp = ws4 + ((size_t)jl << 8);
        #pragma unroll 4
        for (int k = 0; k < 64; k++) {
            float2 x = *reinterpret_cast<const float2*>(&xs[k * 66 + 2 * lane]);
            float4 w = *reinterpret_cast<const float4*>(&wp[k * 4]);
            aR = ffma2(x, make_float2(w.x, w.x), aR);
            aZ = ffma2(x, make_float2(w.y, w.y), aZ);
            aN = ffma2(x, make_float2(w.z, w.z), aN);
        }
    }

    const int j = j0 + jl;
    const float bhr = b_hh[j], bhz = b_hh[j + 512], bhn = b_hh[j + 1024];
    const float* giR = g_giEnc + ((size_t)t * G3 + j) * 64;
    const float* giZ = g_giEnc + ((size_t)t * G3 + j + 512) * 64;
    const float* giN = g_giEnc + ((size_t)t * G3 + j + 1024) * 64;
    float2 hv;
    #pragma unroll
    for (int u = 0; u < 2; u++) {
        int b = 2 * lane + u;
        float ghr = u ? aR.y : aR.x, ghz = u ? aZ.y : aZ.x, ghn = u ? aN.y : aN.x;
        float r = sigf(giR[b] + ghr + bhr);
        float z = sigf(giZ[b] + ghz + bhz);
        float n = tanhf(giN[b] + r * (ghn + bhn));
        float ho = hin[j * 64 + b];
        float v = (t < src_len[b]) ? (1.f - z) * n + z * ho : ho;
        if (u) hv.y = v; else hv.x = v;
    }
    *reinterpret_cast<float2*>(&hout[j * 64 + 2 * lane]) = hv;
}

// ---------------- fused decoder GRU cell: 1 node ----------------
// K layout: [emb 0..255][rate 256][pad..319][h 320..831], 13 tiles of 64.
__global__ __launch_bounds__(128)
void dec_fused(const float* __restrict__ hin, float* __restrict__ hout,
               const float* __restrict__ emb_dec,
               const float* __restrict__ W_ih, const float* __restrict__ W_hh,
               const float* __restrict__ b_ih, const float* __restrict__ b_hh)
{
    __shared__ __align__(16) float xs[64 * 66];
    __shared__ __align__(16) float ws4[4 * 64 * 4];
    const int tid = threadIdx.x;
    const int j0 = blockIdx.x * 4;
    const int jl = tid >> 5, lane = tid & 31;

    float2 aR = make_float2(0.f, 0.f), aZ = aR, aNi = aR, aNh = aR;
    for (int c = 0; c < 13; c++) {
        const int kt = c * 64;
        __syncthreads();
        if (c < 5) {          // input region (gather)
            for (int e = tid; e < 4096; e += 128) {
                int b = e >> 6, kl = e & 63, kk = kt + kl;
                float v = 0.f;
                if (kk < EMB)       v = emb_dec[(size_t)g_idx[b] * EMB + kk];
                else if (kk == EMB) v = g_rate[b];
                xs[kl * 66 + b] = v;
            }
            for (int e = tid; e < 768; e += 128) {
                int jj = e / 192, g = (e >> 6) % 3, k = e & 63, kk = kt + k;
                ws4[((jj << 6) + k) * 4 + g] =
                    (kk < EMB + 1) ? W_ih[(size_t)((g << 9) + j0 + jj) * (EMB + 1) + kk] : 0.f;
            }
        } else {              // hidden region
            int kb = kt - 320;
            for (int e = tid; e < 4096; e += 128) {
                int k = e >> 6, b = e & 63;
                xs[k * 66 + b] = hin[(kb + k) * 64 + b];
            }
            for (int e = tid; e < 768; e += 128) {
                int jj = e / 192, g = (e >> 6) % 3, k = e & 63;
                ws4[((jj << 6) + k) * 4 + g] = W_hh[(size_t)((g << 9) + j0 + jj) * HID + kb + k];
            }
        }
        __syncthreads();
        const float* wp = ws4 + ((size_t)jl << 8);
        if (c < 5) {
            #pragma unroll 4
            for (int k = 0; k < 64; k++) {
                float2 x = *reinterpret_cast<const float2*>(&xs[k * 66 + 2 * lane]);
                float4 w = *reinterpret_cast<const float4*>(&wp[k * 4]);
                aR  = ffma2(x, make_float2(w.x, w.x), aR);
                aZ  = ffma2(x, make_float2(w.y, w.y), aZ);
                aNi = ffma2(x, make_float2(w.z, w.z), aNi);
            }
        } else {
            #pragma unroll 4
            for (int k = 0; k < 64; k++) {
                float2 x = *reinterpret_cast<const float2*>(&xs[k * 66 + 2 * lane]);
                float4 w = *reinterpret_cast<const float4*>(&wp[k * 4]);
                aR  = ffma2(x, make_float2(w.x, w.x), aR);
                aZ  = ffma2(x, make_float2(w.y, w.y), aZ);
                aNh = ffma2(x, make_float2(w.z, w.z), aNh);
            }
        }
    }

    const int j = j0 + jl;
    const float bir = b_ih[j] + b_hh[j], biz = b_ih[j + 512] + b_hh[j + 512];
    const float bin = b_ih[j + 1024], bhn = b_hh[j + 1024];
    float2 hv;
    #pragma unroll
    for (int u = 0; u < 2; u++) {
        int b = 2 * lane + u;
        float r = sigf((u ? aR.y : aR.x) + bir);
        float z = sigf((u ? aZ.y : aZ.x) + biz);
        float n = tanhf(((u ? aNi.y : aNi.x) + bin) + r * ((u ? aNh.y : aNh.x) + bhn));
        float ho = hin[j * 64 + b];
        float v = (1.f - z) * n + z * ho;
        if (u) hv.y = v; else hv.x = v;
    }
    *reinterpret_cast<float2*>(&hout[j * 64 + 2 * lane]) = hv;
}

// ---------------- logits + Yh GEMM (proven <96,192> shape, grid 318) ----------------
__global__ __launch_bounds__(192)
void logits_yh(const float* __restrict__ hT,
               const float* __restrict__ W_eid, const float* __restrict__ b_eid,
               const float* __restrict__ W_r1)
{
    __shared__ float xs[64 * 66];
    __shared__ float ws[96 * 65];
    const int tid = threadIdx.x;
    const int n0 = blockIdx.x * 96;
    const int bpg = tid & 7, cg = tid >> 3;   // cg 0..23

    float2 acc[4][4];
    #pragma unroll
    for (int i = 0; i < 4; i++)
        #pragma unroll
        for (int c = 0; c < 4; c++) acc[i][c] = make_float2(0.f, 0.f);

    for (int kt = 0; kt < HID; kt += 64) {
        __syncthreads();
        for (int e = tid; e < 4096; e += 192) {
            int k = e >> 6, b = e & 63;
            xs[k * 66 + b] = hT[(kt + k) * 64 + b];
        }
        for (int e = tid; e < 96 * 64; e += 192) {
            int nl = e >> 6, k = e & 63;
            int n = n0 + nl;
            float w = 0.f;
            if (n < EID)        w = W_eid[(size_t)n * HID + kt + k];
            else if (n < NLOG)  w = W_r1[(size_t)(n - EID) * 768 + 256 + kt + k];
            ws[nl * 65 + k] = w;
        }
        __syncthreads();
        #pragma unroll 4
        for (int k = 0; k < 64; k++) {
            float2 xv[4];
            #pragma unroll
            for (int i = 0; i < 4; i++)
                xv[i] = *reinterpret_cast<const float2*>(&xs[k * 66 + 2 * (bpg + 8 * i)]);
            #pragma unroll
            for (int c = 0; c < 4; c++) {
                float wv = ws[(cg * 4 + c) * 65 + k];
                float2 wp = make_float2(wv, wv);
                #pragma unroll
                for (int i = 0; i < 4; i++) acc[i][c] = ffma2(xv[i], wp, acc[i][c]);
            }
        }
    }

    #pragma unroll
    for (int c = 0; c < 4; c++) {
        int n = n0 + cg * 4 + c;
        if (n < EID) {
            float bv = b_eid[n];
            #pragma unroll
            for (int i = 0; i < 4; i++) {
                int p = bpg + 8 * i;
                g_logits[(size_t)(2 * p) * EID + n]     = acc[i][c].x + bv;
                g_logits[(size_t)(2 * p + 1) * EID + n] = acc[i][c].y + bv;
            }
        } else if (n < NLOG) {
            int jy = n - EID;
            #pragma unroll
            for (int i = 0; i < 4; i++) {
                int p = bpg + 8 * i;
                g_Yh[(2 * p) * HID + jy]     = acc[i][c].x;
                g_Yh[(2 * p + 1) * HID + jy] = acc[i][c].y;
            }
        }
    }
}

// ---------------- softmax partials: 320 blocks = 64 b x 5 slices of 6000 ----------------
__global__ void softmax_partials(void)
{
    __shared__ float rm[256], rs[256];
    __shared__ int   ri[256];
    const int b = blockIdx.x & 63, sl = blockIdx.x >> 6, tid = threadIdx.x;
    const float* L = g_logits + (size_t)b * EID;
    const int n0 = sl * 6000;

    float m = -3.4e38f, sum = 0.f; int ix = 0x7fffffff;
    for (int n = n0 + tid; n < n0 + 6000; n += 256) {
        float v = L[n];
        if (v > m) { sum = sum * expf(m - v) + 1.f; m = v; ix = n; }
        else       sum += expf(v - m);
    }
    rm[tid] = m; rs[tid] = sum; ri[tid] = ix;
    __syncthreads();
    for (int st = 128; st; st >>= 1) {
        if (tid < st) {
            float m1 = rm[tid], m2 = rm[tid + st], s1 = rs[tid], s2 = rs[tid + st];
            int i1 = ri[tid], i2 = ri[tid + st];
            float M = fmaxf(m1, m2);
            rs[tid] = s1 * expf(m1 - M) + s2 * expf(m2 - M);
            rm[tid] = M;
            ri[tid] = (m2 > m1) ? i2 : ((m1 > m2) ? i1 : min(i1, i2));
        }
        __syncthreads();
    }
    if (tid == 0) {
        g_pm[b * 5 + sl] = rm[0]; g_ps[b * 5 + sl] = rs[0]; g_pi[b * 5 + sl] = ri[0];
    }
}

// merge the 5 per-slice partials of batch b -> (lse, first-argmax)
__device__ __forceinline__ void merge5(int b, float& lse, int& amax) {
    float M = -3.4e38f, S = 0.f; int I = 0x7fffffff;
    #pragma unroll
    for (int sl = 0; sl < 5; sl++) {
        float m2 = g_pm[b * 5 + sl], s2 = g_ps[b * 5 + sl];
        int i2 = g_pi[b * 5 + sl];
        float Mn = fmaxf(M, m2);
        S = S * expf(M - Mn) + s2 * expf(m2 - Mn);
        I = (m2 > M) ? i2 : ((M > m2) ? I : min(I, i2));
        M = Mn;
    }
    lse = M + logf(S);
    amax = I;
}

// ---------------- finish: normalized write + rate head + idx publish (1 node) ----------------
__global__ void finish_kernel(float* __restrict__ out, int row,
                              const float* __restrict__ b_r1, const float* __restrict__ W_r2,
                              const float* __restrict__ b_r2)
{
    __shared__ float sv[256];
    const int b = blockIdx.x & 63, sl = blockIdx.x >> 6, tid = threadIdx.x;
    float lse; int amax; merge5(b, lse, amax);

    const float* L = g_logits + (size_t)b * EID;
    float* O = out + ((size_t)row * B + b) * EID;
    for (int n = sl * 6000 + tid; n < sl * 6000 + 6000; n += 256) O[n] = L[n] - lse;

    if (sl == 0) {
        // rate = sigmoid(relu(mtProj[amax] + Yh[b] + b_r1) . W_r2 + b_r2)
        float a = 0.f;
        #pragma unroll
        for (int q = 0; q < 2; q++) {
            int j = tid + 256 * q;
            float v = g_mtProj[(size_t)amax * HID + j] + g_Yh[b * HID + j] + b_r1[j];
            a += fmaxf(v, 0.f) * W_r2[j];
        }
        sv[tid] = a; __syncthreads();
        for (int st = 128; st; st >>= 1) { if (tid < st) sv[tid] += sv[tid + st]; __syncthreads(); }
        if (tid == 0) {
            float pr = sigf(sv[0] + b_r2[0]);
            out[(size_t)TRG_T * B * EID + (size_t)row * B + b] = pr;
            g_rate[b] = pr;
            g_idx[b] = amax;
        }
    }
}

// ---------------- host launcher ----------------
extern "C" void kernel_launch(void* const* d_in, const int* in_sizes, int n_in,
                              void* d_out, int out_size)
{
    const float* src      = (const float*)d_in[0];
    const int*   src_len  = (const int*)  d_in[1];
    const int*   trg_eid  = (const int*)  d_in[2];
    const float* trg_rate = (const float*)d_in[3];
    const float* W_ih_enc = (const float*)d_in[4];
    const float* W_hh_enc = (const float*)d_in[5];
    const float* b_ih_enc = (const float*)d_in[6];
    const float* b_hh_enc = (const float*)d_in[7];
    const float* emb_dec  = (const float*)d_in[8];
    const float* W_ih_dec = (const float*)d_in[9];
    const float* W_hh_dec = (const float*)d_in[10];
    const float* b_ih_dec = (const float*)d_in[11];
    const float* b_hh_dec = (const float*)d_in[12];
    const float* emb_mt   = (const float*)d_in[13];
    const float* W_eid    = (const float*)d_in[14];
    const float* b_eid    = (const float*)d_in[15];
    const float* W_r1     = (const float*)d_in[16];
    const float* b_r1     = (const float*)d_in[17];
    const float* W_r2     = (const float*)d_in[18];
    const float* b_r2     = (const float*)d_in[19];
    float* out = (float*)d_out;
    float* out_rate = out + (size_t)TRG_T * B * EID;

    float* hT;
    cudaGetSymbolAddress((void**)&hT, g_hT);
    float* hbuf[2] = { hT, hT + HID * B };

    // zero output row 0 (eid + rate)
    cudaMemsetAsync(out, 0, (size_t)B * EID * sizeof(float), 0);
    cudaMemsetAsync(out_rate, 0, B * sizeof(float), 0);

    // one-time prep
    init_state<<<128, 256>>>(trg_eid, trg_rate);
    enc_gi<<<dim3(384, SRC_T), 256>>>(src, W_ih_enc, b_ih_enc);
    transpose_emb<<<dim3(938, 8), 256>>>(emb_mt);
    mtproj_kernel<<<469 * 8, 128>>>(W_r1);

    // ---------- encoder: 128 masked GRU steps, 1 node each ----------
    for (int t = 0; t < SRC_T; t++) {
        enc_fused<<<128, 128>>>(hbuf[t & 1], hbuf[(t + 1) & 1], W_hh_enc, b_hh_enc, src_len, t);
    }

    // ---------- decoder: 49 autoregressive steps, 4 nodes each ----------
    for (int s = 0; s < TRG_T - 1; s++) {
        const int pi = s & 1, po = (s + 1) & 1;
        dec_fused<<<128, 128>>>(hbuf[pi], hbuf[po], emb_dec,
                                W_ih_dec, W_hh_dec, b_ih_dec, b_hh_dec);
        logits_yh<<<LTIL, 192>>>(hbuf[po], W_eid, b_eid, W_r1);
        softmax_partials<<<320, 256>>>();
        finish_kernel<<<320, 256>>>(out, s + 1, b_r1, W_r2, b_r2);
    }
}

// round 13
// speedup vs baseline: 1.7458x; 1.7458x over previous
#include <cuda_runtime.h>
#include <cuda_bf16.h>
#include <string.h>
#include <math.h>

// ---------------- problem constants ----------------
#define EID   30000
#define EMB   256
#define HID   512
#define SRC_T 128
#define TRG_T 50
#define B     64
#define G3    (3*HID)          // 1536
#define NLOG  30512            // 30000 logits cols + 512 Yh cols
#define LTIL  318              // ceil(30512/96)

// ---------------- device state ----------------
__device__ float g_hT[2 * HID * B];                    // hidden, transposed [j][b], double buffered
__device__ float g_giEnc[(size_t)SRC_T * G3 * B];      // encoder gi, [t][j][b] (incl. b_ih)
__device__ float g_logAll[(size_t)(TRG_T - 1) * B * EID];  // raw logits, all steps (368MB)
__device__ float g_lse[(TRG_T - 1) * B];
__device__ float g_embT[(size_t)EMB * EID];            // emb_mt transposed
__device__ float g_mtProj[(size_t)EID * HID];          // W_r1[:, :256] @ emb_mt[v]
__device__ float g_Yh[B * HID];                        // W_r1[:, 256:768] @ h
__device__ float g_rate[B];
__device__ int   g_idx[B];

// ---------------- packed fp32 FMA (sm_100+) ----------------
__device__ __forceinline__ float2 ffma2(float2 a, float2 b, float2 c) {
    unsigned long long ua, ub, uc, ud;
    memcpy(&ua, &a, 8); memcpy(&ub, &b, 8); memcpy(&uc, &c, 8);
    asm("fma.rn.f32x2 %0, %1, %2, %3;" : "=l"(ud) : "l"(ua), "l"(ub), "l"(uc));
    float2 d; memcpy(&d, &ud, 8); return d;
}

__device__ __forceinline__ float sigf(float x) { return 1.f / (1.f + expf(-x)); }

// ---------------- 64x64 micro-kernel (4 pairs x 4 cols / thread, 128 thr) ----------------
__device__ __forceinline__ void mm64_4x4(const float* __restrict__ xs,
                                         const float* __restrict__ ws,
                                         int bpg, int cg, float2 acc[4][4]) {
    #pragma unroll 4
    for (int k = 0; k < 64; k++) {
        float2 xv[4];
        #pragma unroll
        for (int i = 0; i < 4; i++)
            xv[i] = *reinterpret_cast<const float2*>(&xs[k * 66 + 2 * (bpg + 8 * i)]);
        #pragma unroll
        for (int c = 0; c < 4; c++) {
            float w = ws[(cg * 4 + c) * 65 + k];
            float2 wp = make_float2(w, w);
            #pragma unroll
            for (int i = 0; i < 4; i++) acc[i][c] = ffma2(xv[i], wp, acc[i][c]);
        }
    }
}

// store to transposed partial layout [j][b]
__device__ __forceinline__ void store_T(float* __restrict__ dst, int n0,
                                        int bpg, int cg, float2 acc[4][4]) {
    #pragma unroll
    for (int c = 0; c < 4; c++) {
        int j3 = n0 + cg * 4 + c;
        #pragma unroll
        for (int i = 0; i < 4; i++) {
            int p = bpg + 8 * i;
            dst[j3 * 64 + 2 * p]     = acc[i][c].x;
            dst[j3 * 64 + 2 * p + 1] = acc[i][c].y;
        }
    }
}

// ---------------- partial buffers for GRU GEMMs ----------------
__device__ float g_A[8 * G3 * B];                      // gh partials, [p][j][b]
__device__ float g_Bp[5 * G3 * B];                     // gi partials (decoder), [p][j][b]

// ---------------- encoder gh GEMM: grid (24, 8)  [R11 verbatim] ----------------
__global__ __launch_bounds__(128)
void enc_gemm(const float* __restrict__ h, const float* __restrict__ W_hh)
{
    __shared__ float xs[64 * 66];
    __shared__ float ws[64 * 65];
    const int tid = threadIdx.x;
    const int jn = blockIdx.x, jk = blockIdx.y;
    const int n0 = jn * 64, k0 = jk * 64;
    const int bpg = tid & 7, cg = tid >> 3;

    for (int e = tid; e < 4096; e += 128) {
        int k = e >> 6, b = e & 63;
        xs[k * 66 + b] = h[(k0 + k) * 64 + b];
    }
    for (int e = tid; e < 4096; e += 128) {
        int nl = e >> 6, k = e & 63;
        ws[nl * 65 + k] = W_hh[(size_t)(n0 + nl) * HID + k0 + k];
    }
    __syncthreads();

    float2 acc[4][4];
    #pragma unroll
    for (int i = 0; i < 4; i++)
        #pragma unroll
        for (int c = 0; c < 4; c++) acc[i][c] = make_float2(0.f, 0.f);
    mm64_4x4(xs, ws, bpg, cg, acc);
    store_T(g_A + (size_t)jk * G3 * 64, n0, bpg, cg, acc);
}

// ---------------- decoder gi+gh GEMM with fused input gather: grid (24, 13) [R11 verbatim] ----------------
__global__ __launch_bounds__(128)
void dec_gemm_both(const float* __restrict__ h,
                   const float* __restrict__ emb_dec,
                   const float* __restrict__ W_ih, const float* __restrict__ W_hh)
{
    __shared__ float xs[64 * 66];
    __shared__ float ws[64 * 65];
    const int tid = threadIdx.x;
    const int jn = blockIdx.x, jk = blockIdx.y;
    const int n0 = jn * 64;
    const int bpg = tid & 7, cg = tid >> 3;

    if (jk < 5) {
        int kb = jk * 64;
        for (int e = tid; e < 4096; e += 128) {
            int b = e >> 6, kl = e & 63, kk = kb + kl;
            float v = 0.f;
            if (kk < EMB)       v = emb_dec[(size_t)g_idx[b] * EMB + kk];
            else if (kk == EMB) v = g_rate[b];
            xs[kl * 66 + b] = v;
        }
        for (int e = tid; e < 4096; e += 128) {
            int nl = e >> 6, k = e & 63, kk = kb + k;
            ws[nl * 65 + k] = (kk < EMB + 1) ? W_ih[(size_t)(n0 + nl) * (EMB + 1) + kk] : 0.f;
        }
    } else {
        int kb = (jk - 5) * 64;
        for (int e = tid; e < 4096; e += 128) {
            int k = e >> 6, b = e & 63;
            xs[k * 66 + b] = h[(kb + k) * 64 + b];
        }
        for (int e = tid; e < 4096; e += 128) {
            int nl = e >> 6, k = e & 63;
            ws[nl * 65 + k] = W_hh[(size_t)(n0 + nl) * HID + kb + k];
        }
    }
    __syncthreads();

    float2 acc[4][4];
    #pragma unroll
    for (int i = 0; i < 4; i++)
        #pragma unroll
        for (int c = 0; c < 4; c++) acc[i][c] = make_float2(0.f, 0.f);
    mm64_4x4(xs, ws, bpg, cg, acc);
    float* dst = (jk < 5) ? (g_Bp + (size_t)jk * G3 * 64) : (g_A + (size_t)(jk - 5) * G3 * 64);
    store_T(dst, n0, bpg, cg, acc);
}

// ---------------- GRU gate combine [R11 verbatim] ----------------
__global__ void combine_T(const float* __restrict__ Ap, int nA,
                          const float* __restrict__ Bsrc, int nB,
                          const float* __restrict__ b_ih, const float* __restrict__ b_hh,
                          const float* __restrict__ hin, float* __restrict__ hout,
                          const int* __restrict__ src_len, int t)
{
    int i = blockIdx.x * blockDim.x + threadIdx.x;   // 128 x 256 = 32768
    if (i >= B * HID) return;
    const int j = i >> 6, b = i & 63;

    float ar = b_hh[j], az = b_hh[j + 512], an = b_hh[j + 1024];
    #pragma unroll 4
    for (int p = 0; p < nA; p++) {
        const float* a = Ap + (size_t)p * G3 * 64;
        ar += a[j * 64 + b]; az += a[(j + 512) * 64 + b]; an += a[(j + 1024) * 64 + b];
    }
    float br, bz, bn;
    if (nB == 0) {
        br = Bsrc[j * 64 + b]; bz = Bsrc[(j + 512) * 64 + b]; bn = Bsrc[(j + 1024) * 64 + b];
    } else {
        br = b_ih[j]; bz = b_ih[j + 512]; bn = b_ih[j + 1024];
        #pragma unroll 4
        for (int p = 0; p < nB; p++) {
            const float* a = Bsrc + (size_t)p * G3 * 64;
            br += a[j * 64 + b]; bz += a[(j + 512) * 64 + b]; bn += a[(j + 1024) * 64 + b];
        }
    }
    float r = sigf(ar + br);
    float z = sigf(az + bz);
    float n = tanhf(bn + r * an);
    float ho = hin[j * 64 + b];
    float hv = (1.f - z) * n + z * ho;
    if (src_len && !(t < src_len[b])) hv = ho;
    hout[j * 64 + b] = hv;
}

// ---------------- logits + Yh GEMM (proven <96,192> shape, grid 318) ----------------
__global__ __launch_bounds__(192)
void logits_yh(const float* __restrict__ hT,
               const float* __restrict__ W_eid, const float* __restrict__ b_eid,
               const float* __restrict__ W_r1, float* __restrict__ Lout)
{
    __shared__ float xs[64 * 66];
    __shared__ float ws[96 * 65];
    const int tid = threadIdx.x;
    const int n0 = blockIdx.x * 96;
    const int bpg = tid & 7, cg = tid >> 3;   // cg 0..23

    float2 acc[4][4];
    #pragma unroll
    for (int i = 0; i < 4; i++)
        #pragma unroll
        for (int c = 0; c < 4; c++) acc[i][c] = make_float2(0.f, 0.f);

    for (int kt = 0; kt < HID; kt += 64) {
        __syncthreads();
        for (int e = tid; e < 4096; e += 192) {
            int k = e >> 6, b = e & 63;
            xs[k * 66 + b] = hT[(kt + k) * 64 + b];
        }
        for (int e = tid; e < 96 * 64; e += 192) {
            int nl = e >> 6, k = e & 63;
            int n = n0 + nl;
            float w = 0.f;
            if (n < EID)        w = W_eid[(size_t)n * HID + kt + k];
            else if (n < NLOG)  w = W_r1[(size_t)(n - EID) * 768 + 256 + kt + k];
            ws[nl * 65 + k] = w;
        }
        __syncthreads();
        #pragma unroll 4
        for (int k = 0; k < 64; k++) {
            float2 xv[4];
            #pragma unroll
            for (int i = 0; i < 4; i++)
                xv[i] = *reinterpret_cast<const float2*>(&xs[k * 66 + 2 * (bpg + 8 * i)]);
            #pragma unroll
            for (int c = 0; c < 4; c++) {
                float wv = ws[(cg * 4 + c) * 65 + k];
                float2 wp = make_float2(wv, wv);
                #pragma unroll
                for (int i = 0; i < 4; i++) acc[i][c] = ffma2(xv[i], wp, acc[i][c]);
            }
        }
    }

    #pragma unroll
    for (int c = 0; c < 4; c++) {
        int n = n0 + cg * 4 + c;
        if (n < EID) {
            float bv = b_eid[n];
            #pragma unroll
            for (int i = 0; i < 4; i++) {
                int p = bpg + 8 * i;
                Lout[(size_t)(2 * p) * EID + n]     = acc[i][c].x + bv;
                Lout[(size_t)(2 * p + 1) * EID + n] = acc[i][c].y + bv;
            }
        } else if (n < NLOG) {
            int jy = n - EID;
            #pragma unroll
            for (int i = 0; i < 4; i++) {
                int p = bpg + 8 * i;
                g_Yh[(2 * p) * HID + jy]     = acc[i][c].x;
                g_Yh[(2 * p + 1) * HID + jy] = acc[i][c].y;
            }
        }
    }
}

// ---------------- softmax + argmax + rate head, one node (64 blocks x 1024, R3 shape) ----------------
__global__ void softmax_finish(const float* __restrict__ Lbase, int s,
                               const float* __restrict__ b_r1, const float* __restrict__ W_r2,
                               const float* __restrict__ b_r2, float* __restrict__ outRate)
{
    __shared__ float rm[1024], rs[1024];
    __shared__ int   ri[1024];
    const int b = blockIdx.x, tid = threadIdx.x;
    const float* L = Lbase + (size_t)b * EID;

    float m = -3.4e38f, sum = 0.f; int ix = 0x7fffffff;
    for (int n = tid; n < EID; n += 1024) {
        float v = L[n];
        if (v > m) { sum = sum * expf(m - v) + 1.f; m = v; ix = n; }
        else       sum += expf(v - m);
    }
    rm[tid] = m; rs[tid] = sum; ri[tid] = ix;
    __syncthreads();
    for (int st = 512; st; st >>= 1) {
        if (tid < st) {
            float m1 = rm[tid], m2 = rm[tid + st], s1 = rs[tid], s2 = rs[tid + st];
            int i1 = ri[tid], i2 = ri[tid + st];
            float M = fmaxf(m1, m2);
            rs[tid] = s1 * expf(m1 - M) + s2 * expf(m2 - M);
            rm[tid] = M;
            ri[tid] = (m2 > m1) ? i2 : ((m1 > m2) ? i1 : min(i1, i2));
        }
        __syncthreads();
    }
    const float lse = rm[0] + logf(rs[0]);
    const int amax = ri[0];
    __syncthreads();

    // rate = sigmoid(relu(mtProj[amax] + Yh[b] + b_r1) . W_r2 + b_r2)
    if (tid < 512) {
        float v = g_mtProj[(size_t)amax * HID + tid] + g_Yh[b * HID + tid] + b_r1[tid];
        rm[tid] = fmaxf(v, 0.f) * W_r2[tid];
    }
    __syncthreads();
    for (int st = 256; st; st >>= 1) { if (tid < st) rm[tid] += rm[tid + st]; __syncthreads(); }
    if (tid == 0) {
        float pr = sigf(rm[0] + b_r2[0]);
        outRate[b] = pr;
        g_rate[b] = pr;
        g_idx[b] = amax;
        g_lse[s * B + b] = lse;
    }
}

// ---------------- final bulk writeback: all 49 steps of normalized logits ----------------
__global__ void writeback_all(float* __restrict__ out)
{
    const int sb = blockIdx.x;                 // 0 .. 49*64-1
    const int s = sb >> 6, b = sb & 63;
    const float lse = g_lse[s * B + b];
    const float* L = g_logAll + (size_t)sb * EID;
    float* O = out + ((size_t)(s + 1) * B + b) * EID;
    for (int n = threadIdx.x; n < EID; n += 256) O[n] = L[n] - lse;
}

// ---------------- prep kernels ----------------
__global__ void init_state(const int* __restrict__ trg_eid, const float* __restrict__ trg_rate)
{
    int i = blockIdx.x * 256 + threadIdx.x;
    if (i < HID * B) g_hT[i] = 0.f;
    if (i < B) { g_idx[i] = trg_eid[i]; g_rate[i] = trg_rate[i]; }
}

// gi[t][j][b] = b_ih[j] + sum_k src[t][b][k] * W_ih[j][k]
__global__ void enc_gi(const float* __restrict__ src, const float* __restrict__ W_ih,
                       const float* __restrict__ b_ih)
{
    const int j = blockIdx.x * 4 + (threadIdx.x >> 6);
    const int b = threadIdx.x & 63;
    const int t = blockIdx.y;
    const float* x = src + ((size_t)t * 64 + b) * 3;
    float v = b_ih[j] + x[0] * W_ih[j * 3] + x[1] * W_ih[j * 3 + 1] + x[2] * W_ih[j * 3 + 2];
    g_giEnc[((size_t)t * G3 + j) * 64 + b] = v;
}

__global__ void transpose_emb(const float* __restrict__ emb_mt) {
    __shared__ float sm[32][33];
    int v0 = blockIdx.x * 32, k0 = blockIdx.y * 32;
    int tx = threadIdx.x & 31, ty = threadIdx.x >> 5;
    #pragma unroll
    for (int i = 0; i < 32; i += 8) {
        int v = v0 + ty + i;
        sm[ty + i][tx] = (v < EID) ? emb_mt[(size_t)v * EMB + k0 + tx] : 0.f;
    }
    __syncthreads();
    #pragma unroll
    for (int i = 0; i < 32; i += 8) {
        int v = v0 + tx;
        if (v < EID) g_embT[(size_t)(k0 + ty + i) * EID + v] = sm[tx][ty + i];
    }
}

// g_mtProj[v][j] = sum_{k<256} emb_mt[v][k] * W_r1[j][k]   (proven R8 kernel)
__global__ void mtproj_kernel(const float* __restrict__ W_r1) {
    __shared__ float xs[64 * 66];
    __shared__ float ws[64 * 65];
    int tid = threadIdx.x;
    int vt = blockIdx.x % 469, jt = blockIdx.x / 469;
    int v0 = vt * 64, j0 = jt * 64;
    int bpg = tid & 7, cg = tid >> 3;
    float2 acc[4][4];
    #pragma unroll
    for (int i = 0; i < 4; i++)
        #pragma unroll
        for (int c = 0; c < 4; c++) acc[i][c] = make_float2(0.f, 0.f);
    for (int kt = 0; kt < 256; kt += 64) {
        __syncthreads();
        for (int e = tid; e < 4096; e += 128) {
            int k = e >> 6, vl = e & 63; int v = v0 + vl;
            xs[k * 66 + vl] = (v < EID) ? g_embT[(size_t)(kt + k) * EID + v] : 0.f;
        }
        for (int e = tid; e < 4096; e += 128) {
            int nl = e >> 6, k = e & 63;
            ws[nl * 65 + k] = W_r1[(size_t)(j0 + nl) * 768 + kt + k];
        }
        __syncthreads();
        mm64_4x4(xs, ws, bpg, cg, acc);
    }
    #pragma unroll
    for (int c = 0; c < 4; c++) {
        int j = j0 + cg * 4 + c;
        #pragma unroll
        for (int i = 0; i < 4; i++) {
            int v = v0 + 2 * (bpg + 8 * i);
            if (v < EID)     g_mtProj[(size_t)v * HID + j]       = acc[i][c].x;
            if (v + 1 < EID) g_mtProj[(size_t)(v + 1) * HID + j] = acc[i][c].y;
        }
    }
}

// ---------------- host launcher ----------------
extern "C" void kernel_launch(void* const* d_in, const int* in_sizes, int n_in,
                              void* d_out, int out_size)
{
    const float* src      = (const float*)d_in[0];
    const int*   src_len  = (const int*)  d_in[1];
    const int*   trg_eid  = (const int*)  d_in[2];
    const float* trg_rate = (const float*)d_in[3];
    const float* W_ih_enc = (const float*)d_in[4];
    const float* W_hh_enc = (const float*)d_in[5];
    const float* b_ih_enc = (const float*)d_in[6];
    const float* b_hh_enc = (const float*)d_in[7];
    const float* emb_dec  = (const float*)d_in[8];
    const float* W_ih_dec = (const float*)d_in[9];
    const float* W_hh_dec = (const float*)d_in[10];
    const float* b_ih_dec = (const float*)d_in[11];
    const float* b_hh_dec = (const float*)d_in[12];
    const float* emb_mt   = (const float*)d_in[13];
    const float* W_eid    = (const float*)d_in[14];
    const float* b_eid    = (const float*)d_in[15];
    const float* W_r1     = (const float*)d_in[16];
    const float* b_r1     = (const float*)d_in[17];
    const float* W_r2     = (const float*)d_in[18];
    const float* b_r2     = (const float*)d_in[19];
    float* out = (float*)d_out;
    float* out_rate = out + (size_t)TRG_T * B * EID;

    float *hT, *giEnc, *A, *Bp, *logAll;
    cudaGetSymbolAddress((void**)&hT,     g_hT);
    cudaGetSymbolAddress((void**)&giEnc,  g_giEnc);
    cudaGetSymbolAddress((void**)&A,      g_A);
    cudaGetSymbolAddress((void**)&Bp,     g_Bp);
    cudaGetSymbolAddress((void**)&logAll, g_logAll);
    float* hbuf[2] = { hT, hT + HID * B };

    // zero output row 0 (eid + rate)
    cudaMemsetAsync(out, 0, (size_t)B * EID * sizeof(float), 0);
    cudaMemsetAsync(out_rate, 0, B * sizeof(float), 0);

    // one-time prep
    init_state<<<128, 256>>>(trg_eid, trg_rate);
    enc_gi<<<dim3(384, SRC_T), 256>>>(src, W_ih_enc, b_ih_enc);
    transpose_emb<<<dim3(938, 8), 256>>>(emb_mt);
    mtproj_kernel<<<469 * 8, 128>>>(W_r1);

    // ---------- encoder: 128 masked GRU steps (2 nodes/step, R11 verbatim) ----------
    for (int t = 0; t < SRC_T; t++) {
        enc_gemm<<<dim3(24, 8), 128>>>(hbuf[t & 1], W_hh_enc);
        combine_T<<<128, 256>>>(A, 8, giEnc + (size_t)t * G3 * 64, 0,
                                nullptr, b_hh_enc, hbuf[t & 1], hbuf[(t + 1) & 1],
                                src_len, t);
    }

    // ---------- decoder: 49 autoregressive steps (4 nodes/step) ----------
    for (int s = 0; s < TRG_T - 1; s++) {
        const int pi = s & 1, po = (s + 1) & 1;
        float* Ls = logAll + (size_t)s * B * EID;
        dec_gemm_both<<<dim3(24, 13), 128>>>(hbuf[pi], emb_dec, W_ih_dec, W_hh_dec);
        combine_T<<<128, 256>>>(A, 8, Bp, 5, b_ih_dec, b_hh_dec,
                                hbuf[pi], hbuf[po], nullptr, 0);
        logits_yh<<<LTIL, 192>>>(hbuf[po], W_eid, b_eid, W_r1, Ls);
        softmax_finish<<<64, 1024>>>(Ls, s, b_r1, W_r2, b_r2,
                                     out_rate + (size_t)(s + 1) * B);
    }

    // ---------- one bulk normalized writeback for all steps ----------
    writeback_all<<<(TRG_T - 1) * B, 256>>>(out);
}